// round 11
// baseline (speedup 1.0000x reference)
#include <cuda_runtime.h>

#define N2    128
#define MREG  16384
#define START 6
#define RPB   128            // regions per block
#define TPB   512            // 4 roles x 128 regions
#define NBLK  (MREG / RPB)   // 128
#define PAD   132

// smem floats: sSI[PAD] + sPred[RPB*PAD] + sF[RPB*PAD] + sDth[RPB*PAD] + sP1[RPB*16]
#define SMEM_FLOATS (PAD + 3 * RPB * PAD + RPB * 16)
#define SMEM_BYTES  (SMEM_FLOATS * 4)

__device__ float        g_partials[NBLK];
__device__ unsigned int g_count = 0;

// ---- static stage-2 schedule: units encoded (K<<3)|J, grouped by phase ----
// list A (roles 0/1, own tiles {0,2,4,6}), list B (roles 2/3, own {1,3,5,7})
__constant__ unsigned char A_kj[16] = {
    (0<<3)|0,(2<<3)|0,(4<<3)|0,
    (2<<3)|1,(4<<3)|1,(6<<3)|0,
    (2<<3)|2,(4<<3)|2,
    (4<<3)|3,(6<<3)|1,
    (4<<3)|4,
    (6<<3)|2,
    (6<<3)|3,(6<<3)|4,(6<<3)|5,(6<<3)|6
};
__constant__ unsigned char A_off[9] = {0,3,6,8,10,11,12,12,16};
__constant__ unsigned char B_kj[20] = {
    (1<<3)|0,(3<<3)|0,(5<<3)|0,(7<<3)|0,
    (1<<3)|1,(3<<3)|1,(5<<3)|1,
    (3<<3)|2,(5<<3)|2,(7<<3)|1,
    (3<<3)|3,(5<<3)|3,
    (5<<3)|4,(7<<3)|2,
    (5<<3)|5,
    (7<<3)|3,
    (7<<3)|4,(7<<3)|5,(7<<3)|6,(7<<3)|7
};
__constant__ unsigned char B_off[9] = {0,4,7,10,12,14,15,16,20};
// stage-1 split: roles 0/1 take J in [0,a0), roles 2/3 take [a0, p)
__constant__ unsigned char A0tab[8] = {0,0,1,1,2,2,3,3};

__device__ __forceinline__ void load16(float* d, const float* s) {
#pragma unroll
    for (int q = 0; q < 4; ++q)
        *reinterpret_cast<float4*>(d + 4*q) = *reinterpret_cast<const float4*>(s + 4*q);
}
__device__ __forceinline__ void load24(float* d, const float* s) {
#pragma unroll
    for (int q = 0; q < 6; ++q)
        *reinterpret_cast<float4*>(d + 4*q) = *reinterpret_cast<const float4*>(s + 4*q);
}
// acc[iq] += w[iq-jj+16] * pj[jj]   (w holds lags base..base+23, base = 16*dk+8h-16)
__device__ __forceinline__ void mac8x16(float* acc, const float* w, const float* pj) {
#pragma unroll
    for (int jj = 0; jj < 16; ++jj)
#pragma unroll
        for (int iq = 0; iq < 8; ++iq)
            acc[iq] = fmaf(w[iq - jj + 16], pj[jj], acc[iq]);
}

// stage-1 unit: acc += W(p,J,h) * pred[J]
__device__ __forceinline__ void s1_unit(float* acc, const float* sSI_,
                                        const float* myPred, int p, int J, int h) {
    float w[24]; load24(w, sSI_ + 16 * (p - J) + 8 * h - 16);
    float pj[16]; load16(pj, myPred + 16 * J);
    mac8x16(acc, w, pj);
}
// stage-2 off-diag unit: sDth(K,h) += F(K,J,h) * pred[J]  (owner-exclusive RMW)
__device__ __forceinline__ void s2_unit(const float* myF, const float* myPred,
                                        float* dth, int K, int J, int h) {
    float w[24]; load24(w, myF + 16 * (K - J) + 8 * h - 16);
    float pj[16]; load16(pj, myPred + 16 * J);
    float acc[8];
#pragma unroll
    for (int q = 0; q < 2; ++q)
        *reinterpret_cast<float4*>(acc + 4*q) = *reinterpret_cast<const float4*>(dth + 4*q);
    mac8x16(acc, w, pj);
#pragma unroll
    for (int q = 0; q < 2; ++q)
        *reinterpret_cast<float4*>(dth + 4*q) = *reinterpret_cast<const float4*>(acc + 4*q);
}
// stage-2 diagonal unit (within-tile, lags >= 2)
__device__ __forceinline__ void s2_diag(const float* myF, const float* myPred,
                                        float* dth, int K, int h) {
    float pj[16]; load16(pj, myPred + 16 * K);
    float acc[8];
#pragma unroll
    for (int q = 0; q < 2; ++q)
        *reinterpret_cast<float4*>(acc + 4*q) = *reinterpret_cast<const float4*>(dth + 4*q);
    if (h == 0) {
        float fd[8];
#pragma unroll
        for (int d = 2; d < 8; ++d) fd[d] = myF[d];
#pragma unroll
        for (int jj = 0; jj < 6; ++jj)
#pragma unroll
            for (int iq = 0; iq < 8; ++iq)
                if (iq - jj >= 2)
                    acc[iq] = fmaf(fd[iq - jj], pj[jj], acc[iq]);
    } else {
        float fd[16];
#pragma unroll
        for (int d = 2; d < 16; ++d) fd[d] = myF[d];
#pragma unroll
        for (int jj = 0; jj < 14; ++jj)
#pragma unroll
            for (int iq = 0; iq < 8; ++iq)
                if (8 + iq - jj >= 2)
                    acc[iq] = fmaf(fd[8 + iq - jj], pj[jj], acc[iq]);
    }
#pragma unroll
    for (int q = 0; q < 2; ++q)
        *reinterpret_cast<float4*>(dth + 4*q) = *reinterpret_cast<const float4*>(acc + 4*q);
}

__global__ void __launch_bounds__(TPB, 1) npi_fused(
    const float* __restrict__ rt,
    const float* __restrict__ gt,
    const float* __restrict__ SI,
    const float* __restrict__ f,
    const float* __restrict__ seed,
    float* __restrict__ out)
{
    extern __shared__ float sm[];
    float* sSI   = sm;                       // [PAD]
    float* sPred = sm + PAD;                 // [RPB][PAD]
    float* sF    = sPred + RPB * PAD;        // [RPB][PAD] f_eff rows
    float* sDth  = sF + RPB * PAD;           // [RPB][PAD] stage-2 accumulators
    float* sP1   = sDth + RPB * PAD;         // [RPB][16]  stage-1 partials (L,H)

    const int tid   = threadIdx.x;
    const int g     = tid >> 7;              // role 0..3
    const int rid   = tid & (RPB - 1);
    const int h     = g & 1;                 // half: roles 0,2 -> low; 1,3 -> high
    const bool lstA = (g < 2);
    const int m     = blockIdx.x * RPB + rid;

    float* myPred = sPred + rid * PAD;
    float* myF    = sF + rid * PAD;
    float* myDth  = sDth + rid * PAD;
    float* myP1   = sP1 + rid * 16;

    // ---- staging ----
    {
        const int k0 = g * 32;
#pragma unroll 8
        for (int k = k0; k < k0 + 32; ++k)
            myF[k] = (k < 2) ? 0.0f : f[k * MREG + m];   // f_eff
    }
    if (g == 0) sSI[rid] = SI[rid];
    if (g == 1 && rid < PAD - N2) sSI[N2 + rid] = 0.0f;
    for (int idx = tid; idx < RPB * PAD; idx += TPB) sDth[idx] = 0.0f;
    __syncthreads();

    float siL[16];
    if (g < 2) {
#pragma unroll
        for (int d = 1; d < 16; ++d) siL[d] = sSI[d];
    }

    // ---- prologue: role 0 computes full tile 0 (seeds + triangular) ----
    if (g == 0) {
        float rtt0[16];
#pragma unroll
        for (int ii = START; ii < 16; ++ii) rtt0[ii] = rt[ii * MREG + m];
        float pt[16], s[16];
#pragma unroll
        for (int ii = 0; ii < START; ++ii) pt[ii] = seed[ii * MREG + m];
#pragma unroll
        for (int ii = START; ii < 16; ++ii) s[ii] = 0.f;
#pragma unroll
        for (int jj = 0; jj < 16; ++jj) {
            if (jj >= START) pt[jj] = rtt0[jj] * s[jj];
#pragma unroll
            for (int ii = (jj + 1 > START ? jj + 1 : START); ii < 16; ++ii)
                s[ii] = fmaf(siL[ii - jj], pt[jj], s[ii]);
        }
#pragma unroll
        for (int q = 0; q < 4; ++q)
            *reinterpret_cast<float4*>(myPred + 4*q) =
                make_float4(pt[4*q], pt[4*q+1], pt[4*q+2], pt[4*q+3]);
    }
    __syncthreads();

    const unsigned char* kj  = lstA ? A_kj : B_kj;
    const unsigned char* off = lstA ? A_off : B_off;

    // ---- phases 1..7: stage-1 tile p + scheduled stage-2 units ----
#pragma unroll 1
    for (int p = 1; p < 8; ++p) {
        float s1acc[8] = {0,0,0,0,0,0,0,0};
        float rtt[8];
        if (g < 2) {
#pragma unroll
            for (int q = 0; q < 8; ++q)
                rtt[q] = rt[(16 * p + 8 * h + q) * MREG + m];
        }
        const int a0  = A0tab[p];
        const int jlo = (g < 2) ? 0 : a0;
        const int jhi = (g < 2) ? a0 : p;
        for (int J = jlo; J < jhi; ++J)
            s1_unit(s1acc, sSI, myPred, p, J, h);
        if (g >= 2) {   // write partial for roles 0/1 to combine
#pragma unroll
            for (int q = 0; q < 2; ++q)
                *reinterpret_cast<float4*>(myP1 + 8 * h + 4*q) =
                    make_float4(s1acc[4*q], s1acc[4*q+1], s1acc[4*q+2], s1acc[4*q+3]);
        }
        __syncthreads();   // B1

        if (g == 0) {      // triangular (low half) while others run stage-2
            float acc[8];
#pragma unroll
            for (int q = 0; q < 8; ++q) acc[q] = s1acc[q] + myP1[q];
            float pt[8];
#pragma unroll
            for (int jj = 0; jj < 8; ++jj) {
                pt[jj] = rtt[jj] * acc[jj];
#pragma unroll
                for (int iq = jj + 1; iq < 8; ++iq)
                    acc[iq] = fmaf(siL[iq - jj], pt[jj], acc[iq]);
            }
#pragma unroll
            for (int q = 0; q < 2; ++q)
                *reinterpret_cast<float4*>(myPred + 16 * p + 4*q) =
                    make_float4(pt[4*q], pt[4*q+1], pt[4*q+2], pt[4*q+3]);
        } else {           // roles 1,2,3: this phase's stage-2 units
            for (int u = off[p - 1]; u < off[p]; ++u) {
                const int K = kj[u] >> 3, J = kj[u] & 7;
                float* dth = myDth + 16 * K + 8 * h;
                if (J == K) s2_diag(myF, myPred, dth, K, h);
                else        s2_unit(myF, myPred, dth, K, J, h);
            }
        }
        __syncthreads();   // B2

        if (g == 1) {      // cross terms + triangular (high half)
            float acc[8];
#pragma unroll
            for (int q = 0; q < 8; ++q) acc[q] = s1acc[q] + myP1[8 + q];
            float ptL[8];
#pragma unroll
            for (int q = 0; q < 2; ++q)
                *reinterpret_cast<float4*>(ptL + 4*q) =
                    *reinterpret_cast<const float4*>(myPred + 16 * p + 4*q);
#pragma unroll
            for (int jj = 0; jj < 8; ++jj)
#pragma unroll
                for (int iq = 0; iq < 8; ++iq)
                    acc[iq] = fmaf(siL[iq + 8 - jj], ptL[jj], acc[iq]);
            float pt[8];
#pragma unroll
            for (int jj = 0; jj < 8; ++jj) {
                pt[jj] = rtt[jj] * acc[jj];
#pragma unroll
                for (int iq = jj + 1; iq < 8; ++iq)
                    acc[iq] = fmaf(siL[iq - jj], pt[jj], acc[iq]);
            }
#pragma unroll
            for (int q = 0; q < 2; ++q)
                *reinterpret_cast<float4*>(myPred + 16 * p + 8 + 4*q) =
                    make_float4(pt[4*q], pt[4*q+1], pt[4*q+2], pt[4*q+3]);
        } else if (g == 0) {   // role 0's stage-2 units overlap tri-high
            for (int u = off[p - 1]; u < off[p]; ++u) {
                const int K = kj[u] >> 3, J = kj[u] & 7;
                float* dth = myDth + 16 * K + 8 * h;
                if (J == K) s2_diag(myF, myPred, dth, K, h);
                else        s2_unit(myF, myPred, dth, K, J, h);
            }
        }
        __syncthreads();   // B3
    }

    // ---- phase 8: remaining stage-2 units (all roles) ----
    for (int u = off[7]; u < off[8]; ++u) {
        const int K = kj[u] >> 3, J = kj[u] & 7;
        float* dth = myDth + 16 * K + 8 * h;
        if (J == K) s2_diag(myF, myPred, dth, K, h);
        else        s2_unit(myF, myPred, dth, K, J, h);
    }
    // owner-exclusive accumulators -> no barrier needed before MSE

    // ---- MSE over owned tiles ----
    float loss = 0.f;
#pragma unroll
    for (int t = 0; t < 4; ++t) {
        const int K = 2 * t + (lstA ? 0 : 1);
        float gtt[8];
#pragma unroll
        for (int q = 0; q < 8; ++q)
            gtt[q] = gt[(16 * K + 8 * h + q) * MREG + m];
        float dv[8];
#pragma unroll
        for (int q = 0; q < 2; ++q)
            *reinterpret_cast<float4*>(dv + 4*q) =
                *reinterpret_cast<const float4*>(myDth + 16 * K + 8 * h + 4*q);
#pragma unroll
        for (int q = 0; q < 8; ++q) {
            const int i = 16 * K + 8 * h + q;
            float dp = dv[q];
            if (i < START) dp = (i == 0) ? 1e-9f : 0.f;
            const float diff = dp - gtt[q];
            loss = fmaf(diff, diff, loss);
        }
    }

    // ---- deterministic fused reduction ----
#pragma unroll
    for (int o = 16; o; o >>= 1)
        loss += __shfl_xor_sync(0xffffffffu, loss, o);
    __shared__ float warpsum[TPB / 32];
    __shared__ bool  s_last;
    if ((tid & 31) == 0) warpsum[tid >> 5] = loss;
    __syncthreads();
    if (tid == 0) {
        float s = 0.f;
#pragma unroll
        for (int w = 0; w < TPB / 32; ++w) s += warpsum[w];
        g_partials[blockIdx.x] = s;
        __threadfence();
        unsigned prev = atomicAdd(&g_count, 1u);
        s_last = (prev == NBLK - 1u);
    }
    __syncthreads();
    if (s_last && tid < 32) {
        float v = 0.f;
#pragma unroll
        for (int k = 0; k < NBLK / 32; ++k)
            v += g_partials[tid + k * 32];
#pragma unroll
        for (int o = 16; o; o >>= 1)
            v += __shfl_xor_sync(0xffffffffu, v, o);
        if (tid == 0) {
            out[0] = v * (1.0f / ((float)N2 * (float)MREG));
            g_count = 0;   // reset for graph replay
        }
    }
}

extern "C" void kernel_launch(void* const* d_in, const int* in_sizes, int n_in,
                              void* d_out, int out_size)
{
    const float* rt   = (const float*)d_in[0];
    const float* gt   = (const float*)d_in[1];
    const float* SI   = (const float*)d_in[2];
    const float* f    = (const float*)d_in[3];
    const float* seed = (const float*)d_in[4];

    static bool attr_set = false;
    if (!attr_set) {
        cudaFuncSetAttribute(npi_fused,
                             cudaFuncAttributeMaxDynamicSharedMemorySize,
                             SMEM_BYTES);
        attr_set = true;
    }

    npi_fused<<<NBLK, TPB, SMEM_BYTES>>>(rt, gt, SI, f, seed, (float*)d_out);
}

// round 12
// speedup vs baseline: 1.2771x; 1.2771x over previous
#include <cuda_runtime.h>

#define N2    128
#define MREG  16384
#define START 6
#define RPB   128            // regions per block
#define TPB   512            // 4 roles x 128 regions
#define NBLK  (MREG / RPB)   // 128
#define T     16
#define NT    (N2 / T)       // 8
#define PAD   132

// smem floats: sSI[PAD] + sPred[RPB*PAD] + sF[RPB*PAD]
#define SMEM_FLOATS (PAD + 2 * RPB * PAD)
#define SMEM_BYTES  (SMEM_FLOATS * 4)

__device__ float        g_partials[NBLK];
__device__ unsigned int g_count = 0;

__device__ __forceinline__ void load16(float* d, const float* s) {
#pragma unroll
    for (int q = 0; q < 4; ++q)
        *reinterpret_cast<float4*>(d + 4*q) = *reinterpret_cast<const float4*>(s + 4*q);
}
__device__ __forceinline__ void load24(float* d, const float* s) {
#pragma unroll
    for (int q = 0; q < 6; ++q)
        *reinterpret_cast<float4*>(d + 4*q) = *reinterpret_cast<const float4*>(s + 4*q);
}
// acc[iq] += w[iq-jj+16] * pj[jj]
__device__ __forceinline__ void mac8x16(float* acc, const float* w, const float* pj) {
#pragma unroll
    for (int jj = 0; jj < 16; ++jj)
#pragma unroll
        for (int iq = 0; iq < 8; ++iq)
            acc[iq] = fmaf(w[iq - jj + 16], pj[jj], acc[iq]);
}

// fully-unrolled history matvec: CNT units, J descending (k ascending).
// wrow already includes the half offset (8h). Unit k: window wrow+16k,
// pred tile J = CNT-1-k. Same FP order as the R8 loop.
template<int CNT>
__device__ __forceinline__ void histmac(float* acc, const float* wrow,
                                        const float* predRow) {
#pragma unroll
    for (int k = 0; k < CNT; ++k) {
        float w[24];  load24(w,  wrow + 16 * k);
        float pj[16]; load16(pj, predRow + 16 * (CNT - 1 - k));
        mac8x16(acc, w, pj);
    }
}
__device__ __forceinline__ void hist_dispatch(int n, float* acc,
                                              const float* wrow,
                                              const float* predRow) {
    switch (n) {
        case 1: histmac<1>(acc, wrow, predRow); break;
        case 2: histmac<2>(acc, wrow, predRow); break;
        case 3: histmac<3>(acc, wrow, predRow); break;
        case 4: histmac<4>(acc, wrow, predRow); break;
        case 5: histmac<5>(acc, wrow, predRow); break;
        case 6: histmac<6>(acc, wrow, predRow); break;
        case 7: histmac<7>(acc, wrow, predRow); break;
        default: break;
    }
}

__global__ void __launch_bounds__(TPB, 1) npi_fused(
    const float* __restrict__ rt,
    const float* __restrict__ gt,
    const float* __restrict__ SI,
    const float* __restrict__ f,
    const float* __restrict__ seed,
    float* __restrict__ out)
{
    extern __shared__ float sm[];
    float* sSI   = sm;                 // [PAD]
    float* sPred = sm + PAD;           // [RPB][PAD]
    float* sF    = sPred + RPB * PAD;  // [RPB][PAD] f_eff rows

    const int tid = threadIdx.x;
    const int g   = tid >> 7;          // role: 0=P0,1=P1,2=C0,3=C1
    const int rid = tid & (RPB - 1);
    const int h8  = (g & 1) ? 8 : 0;   // half offset within tile
    const int m   = blockIdx.x * RPB + rid;

    float* myPred = sPred + rid * PAD;
    float* myF    = sF + rid * PAD;

    // ---- staging: f coalesced by all roles, SI by role 0 -------------------
    {
        const int k0 = g * 32;
#pragma unroll 8
        for (int k = k0; k < k0 + 32; ++k)
            myF[k] = (k < 2) ? 0.0f : f[k * MREG + m];   // f_eff
    }
    if (g == 0) sSI[rid] = SI[rid];
    if (g == 1 && rid < PAD - N2) sSI[N2 + rid] = 0.0f;
    __syncthreads();

    float siL[T];          // producers
    float fL[T];           // consumers
    float loss = 0.f;

    if (g <= 1) {
#pragma unroll
        for (int d = 1; d < T; ++d) siL[d] = sSI[d];
    } else {
#pragma unroll
        for (int d = 2; d < T; ++d) fL[d] = myF[d];
    }

    // ---- tile 0: P0 computes full seed tile --------------------------------
    if (g == 0) {
        float rtt[T];
#pragma unroll
        for (int ii = START; ii < T; ++ii) rtt[ii] = rt[ii * MREG + m];
        float pt[T], s[T];
#pragma unroll
        for (int ii = 0; ii < START; ++ii) pt[ii] = seed[ii * MREG + m];
#pragma unroll
        for (int ii = START; ii < T; ++ii) s[ii] = 0.f;
#pragma unroll
        for (int jj = 0; jj < T; ++jj) {
            if (jj >= START) pt[jj] = rtt[jj] * s[jj];
#pragma unroll
            for (int ii = (jj + 1 > START ? jj + 1 : START); ii < T; ++ii)
                s[ii] = fmaf(siL[ii - jj], pt[jj], s[ii]);
        }
#pragma unroll
        for (int q = 0; q < 4; ++q)
            *reinterpret_cast<float4*>(myPred + 4*q) =
                make_float4(pt[4*q], pt[4*q+1], pt[4*q+2], pt[4*q+3]);
    }
    __syncthreads();

    // ---- pipelined phases: producers build tile I, consumers eat tile I-1 --
#pragma unroll 1
    for (int I = 1; I <= NT; ++I) {
        if (g < 2) {
            if (I < NT) {
                const int c = I * T;
                float rtt[8];
#pragma unroll
                for (int q = 0; q < 8; ++q)
                    rtt[q] = rt[(c + h8 + q) * MREG + m];

                float acc[8] = {0,0,0,0,0,0,0,0};
                hist_dispatch(I, acc, sSI + h8, myPred);

                if (g == 0) {
                    // triangular low half, store
                    float pt[8];
#pragma unroll
                    for (int jj = 0; jj < 8; ++jj) {
                        pt[jj] = rtt[jj] * acc[jj];
#pragma unroll
                        for (int iq = jj + 1; iq < 8; ++iq)
                            acc[iq] = fmaf(siL[iq - jj], pt[jj], acc[iq]);
                    }
#pragma unroll
                    for (int q = 0; q < 2; ++q)
                        *reinterpret_cast<float4*>(myPred + c + 4*q) =
                            make_float4(pt[4*q], pt[4*q+1], pt[4*q+2], pt[4*q+3]);
                }

                // producer-only handoff barrier (threads 0..255 = warps 0..7)
                asm volatile("bar.sync 1, 256;" ::: "memory");

                if (g == 1) {
                    // cross terms from P0's low half + triangular high half
                    float ptL[8];
#pragma unroll
                    for (int q = 0; q < 2; ++q)
                        *reinterpret_cast<float4*>(ptL + 4*q) =
                            *reinterpret_cast<const float4*>(myPred + c + 4*q);
#pragma unroll
                    for (int jj = 0; jj < 8; ++jj)
#pragma unroll
                        for (int iq = 0; iq < 8; ++iq)
                            acc[iq] = fmaf(siL[iq + 8 - jj], ptL[jj], acc[iq]);
                    float pt[8];
#pragma unroll
                    for (int jj = 0; jj < 8; ++jj) {
                        pt[jj] = rtt[jj] * acc[jj];
#pragma unroll
                        for (int iq = jj + 1; iq < 8; ++iq)
                            acc[iq] = fmaf(siL[iq - jj], pt[jj], acc[iq]);
                    }
#pragma unroll
                    for (int q = 0; q < 2; ++q)
                        *reinterpret_cast<float4*>(myPred + c + 8 + 4*q) =
                            make_float4(pt[4*q], pt[4*q+1], pt[4*q+2], pt[4*q+3]);
                }
            }
        } else {
            // consumers: full output tile IC = I-1 (off-diag + diag + MSE),
            // no mid-phase barrier participation.
            const int IC = I - 1;
            const int c2 = IC * T;
            float gtt[8];
#pragma unroll
            for (int q = 0; q < 8; ++q)
                gtt[q] = gt[(c2 + h8 + q) * MREG + m];

            float dacc[8] = {0,0,0,0,0,0,0,0};
            if (IC >= 1)
                hist_dispatch(IC, dacc, myF + h8, myPred);

            // diagonal tile: lags >= 2 within tile IC
            float pd[T];
            load16(pd, myPred + c2);
            if (h8 == 0) {
#pragma unroll
                for (int jj = 0; jj < T; ++jj)
#pragma unroll
                    for (int iq = 0; iq < 8; ++iq)
                        if (iq - jj >= 2)
                            dacc[iq] = fmaf(fL[iq - jj], pd[jj], dacc[iq]);
            } else {
#pragma unroll
                for (int jj = 0; jj < T; ++jj)
#pragma unroll
                    for (int iq = 0; iq < 8; ++iq)
                        if (8 + iq - jj >= 2 && 8 + iq - jj <= 15)
                            dacc[iq] = fmaf(fL[8 + iq - jj], pd[jj], dacc[iq]);
            }

#pragma unroll
            for (int iq = 0; iq < 8; ++iq) {
                const int i = c2 + h8 + iq;
                float dp = dacc[iq];
                if (i < START) dp = (i == 0) ? 1e-9f : 0.f;
                const float diff = dp - gtt[iq];
                loss = fmaf(diff, diff, loss);
            }
        }
        __syncthreads();   // end of phase: tile I published to everyone
    }

    // ---- deterministic fused reduction --------------------------------------
#pragma unroll
    for (int o = 16; o; o >>= 1)
        loss += __shfl_xor_sync(0xffffffffu, loss, o);
    __shared__ float warpsum[TPB / 32];
    __shared__ bool  s_last;
    if ((tid & 31) == 0) warpsum[tid >> 5] = loss;
    __syncthreads();
    if (tid == 0) {
        float s = 0.f;
#pragma unroll
        for (int w = 0; w < TPB / 32; ++w) s += warpsum[w];
        g_partials[blockIdx.x] = s;
        __threadfence();
        unsigned prev = atomicAdd(&g_count, 1u);
        s_last = (prev == NBLK - 1u);
    }
    __syncthreads();
    if (s_last && tid < 32) {
        float v = 0.f;
#pragma unroll
        for (int k = 0; k < NBLK / 32; ++k)
            v += g_partials[tid + k * 32];
#pragma unroll
        for (int o = 16; o; o >>= 1)
            v += __shfl_xor_sync(0xffffffffu, v, o);
        if (tid == 0) {
            out[0] = v * (1.0f / ((float)N2 * (float)MREG));
            g_count = 0;   // reset for graph replay
        }
    }
}

extern "C" void kernel_launch(void* const* d_in, const int* in_sizes, int n_in,
                              void* d_out, int out_size)
{
    const float* rt   = (const float*)d_in[0];
    const float* gt   = (const float*)d_in[1];
    const float* SI   = (const float*)d_in[2];
    const float* f    = (const float*)d_in[3];
    const float* seed = (const float*)d_in[4];

    static bool attr_set = false;
    if (!attr_set) {
        cudaFuncSetAttribute(npi_fused,
                             cudaFuncAttributeMaxDynamicSharedMemorySize,
                             SMEM_BYTES);
        attr_set = true;
    }

    npi_fused<<<NBLK, TPB, SMEM_BYTES>>>(rt, gt, SI, f, seed, (float*)d_out);
}